// round 1
// baseline (speedup 1.0000x reference)
#include <cuda_runtime.h>
#include <cstdint>
#include <cstdio>

// ---------------------------------------------------------------------------
// MessagePassing hand-graph GNN, fused 3-layer MLP per node.
// Round 1: warp-level mma.sync tf32 (m16n8k8), fp32 accumulate.
// CTA = 128 batch rows x 1 node. grid = (21 nodes, B/128).
// ---------------------------------------------------------------------------

struct Params {
    const float* x;
    const float* w1[5]; const float* b1[5];
    const float* w2[5]; const float* b2[5];
    const float* w3[5]; const float* b3[5];
    float* out;
};

// Node tables: groups ordered [n=6, n=5, n=4, n=3, n=2], rows in reference order.
__constant__ int c_gi[21]  = {0,1,1,1,2,2,3,3,3,3,3,3,3,3,3,3,4,4,4,4,4};
__constant__ int c_ki[21]  = {0,0,1,2,0,1,0,1,2,3,4,5,6,7,8,9,0,1,2,3,4};
__constant__ int c_n[21]   = {6,5,5,5,4,4,3,3,3,3,3,3,3,3,3,3,2,2,2,2,2};
__constant__ int c_out[21] = {0,5,9,13,1,17,2,3,6,7,10,11,14,15,18,19,4,8,12,16,20};
__constant__ int c_nb[21][6] = {
    {0,1,5,9,13,17},
    {0,5,6,1,9,0},  {0,9,10,5,13,0}, {0,13,14,9,17,0},
    {0,1,2,5,0,0},  {0,17,18,13,0,0},
    {1,2,3,0,0,0},  {2,3,4,0,0,0},
    {5,6,7,0,0,0},  {6,7,8,0,0,0},
    {9,10,11,0,0,0},{10,11,12,0,0,0},
    {13,14,15,0,0,0},{14,15,16,0,0,0},
    {17,18,19,0,0,0},{18,19,20,0,0,0},
    {3,4,0,0,0,0},  {7,8,0,0,0,0}, {11,12,0,0,0,0},
    {15,16,0,0,0,0},{19,20,0,0,0,0}
};

#define XS_STRIDE 68     // 68 % 32 = 4  -> A-frag LDS conflict-free (4g + t4)
#define WS_STRIDE 136    // 136 % 32 = 8 -> B-frag LDS conflict-free (8t4 + g)
#define HS_STRIDE 132    // 132 % 32 = 4 -> A-frag LDS conflict-free
#define SMEM_BYTES ((128*XS_STRIDE + 128*WS_STRIDE + 128*HS_STRIDE) * 4)

__device__ __forceinline__ uint32_t f2tf(float f) {
    uint32_t r;
    asm("cvt.rna.tf32.f32 %0, %1;" : "=r"(r) : "f"(f));
    return r;
}

__device__ __forceinline__ void mma8(float c[4],
                                     uint32_t a0, uint32_t a1, uint32_t a2, uint32_t a3,
                                     uint32_t b0, uint32_t b1) {
    asm volatile(
        "mma.sync.aligned.m16n8k8.row.col.f32.tf32.tf32.f32 "
        "{%0,%1,%2,%3},{%4,%5,%6,%7},{%8,%9},{%0,%1,%2,%3};"
        : "+f"(c[0]), "+f"(c[1]), "+f"(c[2]), "+f"(c[3])
        : "r"(a0), "r"(a1), "r"(a2), "r"(a3), "r"(b0), "r"(b1));
}

__global__ __launch_bounds__(256, 1)
void mp_kernel(Params p) {
    extern __shared__ float smem[];
    float* Xs = smem;                                   // [128][68]
    float* Ws = smem + 128 * XS_STRIDE;                 // [128][136]
    float* Hs = smem + 128 * (XS_STRIDE + WS_STRIDE);   // [128][132]

    const int node = blockIdx.x;
    const int m0   = blockIdx.y * 128;
    const int tid  = threadIdx.x;
    const int w    = tid >> 5;
    const int lane = tid & 31;
    const int g    = lane >> 2;   // 0..7
    const int t4   = lane & 3;    // 0..3
    const int gi   = c_gi[node];
    const int ki   = c_ki[node];
    const int nnb  = c_n[node];

    // layers 1-2 warp grid: 2 (M) x 4 (N)
    const int wm = w & 1;         // row half: 64 rows
    const int wn = w >> 1;        // col quarter: 32 cols

    float acc[4][4][4];
    #pragma unroll
    for (int mi = 0; mi < 4; ++mi)
        #pragma unroll
        for (int ni = 0; ni < 4; ++ni)
            #pragma unroll
            for (int r = 0; r < 4; ++r) acc[mi][ni][r] = 0.f;

    // ======================= Layer 1: H1 = relu(Xg*W1 + b1) =================
    const float* W1 = p.w1[gi] + (size_t)ki * (size_t)nnb * 64 * 128;
    #pragma unroll 1
    for (int cchunk = 0; cchunk < nnb; ++cchunk) {
        if (cchunk) __syncthreads();
        const int jo = c_nb[node][cchunk] * 64;
        // X chunk: 128 rows x 64 cols (gathered joint)
        #pragma unroll
        for (int i = 0; i < 8; ++i) {
            int t = tid + i * 256;
            int r = t >> 4, q = (t & 15) << 2;
            *(float4*)(Xs + r * XS_STRIDE + q) =
                *(const float4*)(p.x + (size_t)(m0 + r) * 1344 + jo + q);
        }
        // W1 chunk: 64 rows (K) x 128 cols (N)
        #pragma unroll
        for (int i = 0; i < 8; ++i) {
            int t = tid + i * 256;
            int r = t >> 5, q = (t & 31) << 2;
            *(float4*)(Ws + r * WS_STRIDE + q) =
                *(const float4*)(W1 + (size_t)(cchunk * 64 + r) * 128 + q);
        }
        __syncthreads();
        #pragma unroll 4
        for (int ks = 0; ks < 8; ++ks) {
            int k0 = ks * 8;
            uint32_t a[4][4];
            #pragma unroll
            for (int mi = 0; mi < 4; ++mi) {
                int r0 = wm * 64 + mi * 16;
                a[mi][0] = f2tf(Xs[(r0 + g)     * XS_STRIDE + k0 + t4]);
                a[mi][1] = f2tf(Xs[(r0 + g + 8) * XS_STRIDE + k0 + t4]);
                a[mi][2] = f2tf(Xs[(r0 + g)     * XS_STRIDE + k0 + t4 + 4]);
                a[mi][3] = f2tf(Xs[(r0 + g + 8) * XS_STRIDE + k0 + t4 + 4]);
            }
            #pragma unroll
            for (int ni = 0; ni < 4; ++ni) {
                int n0 = wn * 32 + ni * 8;
                uint32_t b0 = f2tf(Ws[(k0 + t4)     * WS_STRIDE + n0 + g]);
                uint32_t b1 = f2tf(Ws[(k0 + t4 + 4) * WS_STRIDE + n0 + g]);
                #pragma unroll
                for (int mi = 0; mi < 4; ++mi)
                    mma8(acc[mi][ni], a[mi][0], a[mi][1], a[mi][2], a[mi][3], b0, b1);
            }
        }
    }
    __syncthreads();  // all Xs/Ws reads done

    // epilogue 1: bias + relu -> Hs
    {
        const float* bp = p.b1[gi] + ki * 128;
        #pragma unroll
        for (int ni = 0; ni < 4; ++ni) {
            int n0 = wn * 32 + ni * 8 + 2 * t4;
            float bb0 = bp[n0], bb1 = bp[n0 + 1];
            #pragma unroll
            for (int mi = 0; mi < 4; ++mi) {
                int r0 = wm * 64 + mi * 16 + g;
                Hs[r0 * HS_STRIDE + n0]           = fmaxf(acc[mi][ni][0] + bb0, 0.f);
                Hs[r0 * HS_STRIDE + n0 + 1]       = fmaxf(acc[mi][ni][1] + bb1, 0.f);
                Hs[(r0 + 8) * HS_STRIDE + n0]     = fmaxf(acc[mi][ni][2] + bb0, 0.f);
                Hs[(r0 + 8) * HS_STRIDE + n0 + 1] = fmaxf(acc[mi][ni][3] + bb1, 0.f);
                acc[mi][ni][0] = acc[mi][ni][1] = acc[mi][ni][2] = acc[mi][ni][3] = 0.f;
            }
        }
    }
    // load W2 (128x128)
    {
        const float* W2 = p.w2[gi] + (size_t)ki * 128 * 128;
        #pragma unroll
        for (int i = 0; i < 16; ++i) {
            int t = tid + i * 256;
            int r = t >> 5, q = (t & 31) << 2;
            *(float4*)(Ws + r * WS_STRIDE + q) = *(const float4*)(W2 + r * 128 + q);
        }
    }
    __syncthreads();

    // ======================= Layer 2: H2 = relu(H1*W2 + b2) =================
    #pragma unroll 4
    for (int ks = 0; ks < 16; ++ks) {
        int k0 = ks * 8;
        uint32_t a[4][4];
        #pragma unroll
        for (int mi = 0; mi < 4; ++mi) {
            int r0 = wm * 64 + mi * 16;
            a[mi][0] = f2tf(Hs[(r0 + g)     * HS_STRIDE + k0 + t4]);
            a[mi][1] = f2tf(Hs[(r0 + g + 8) * HS_STRIDE + k0 + t4]);
            a[mi][2] = f2tf(Hs[(r0 + g)     * HS_STRIDE + k0 + t4 + 4]);
            a[mi][3] = f2tf(Hs[(r0 + g + 8) * HS_STRIDE + k0 + t4 + 4]);
        }
        #pragma unroll
        for (int ni = 0; ni < 4; ++ni) {
            int n0 = wn * 32 + ni * 8;
            uint32_t b0 = f2tf(Ws[(k0 + t4)     * WS_STRIDE + n0 + g]);
            uint32_t b1 = f2tf(Ws[(k0 + t4 + 4) * WS_STRIDE + n0 + g]);
            #pragma unroll
            for (int mi = 0; mi < 4; ++mi)
                mma8(acc[mi][ni], a[mi][0], a[mi][1], a[mi][2], a[mi][3], b0, b1);
        }
    }
    __syncthreads();  // all Hs/Ws reads done

    // epilogue 2: bias + relu -> Hs ; load W3 (128x64)
    {
        const float* bp = p.b2[gi] + ki * 128;
        #pragma unroll
        for (int ni = 0; ni < 4; ++ni) {
            int n0 = wn * 32 + ni * 8 + 2 * t4;
            float bb0 = bp[n0], bb1 = bp[n0 + 1];
            #pragma unroll
            for (int mi = 0; mi < 4; ++mi) {
                int r0 = wm * 64 + mi * 16 + g;
                Hs[r0 * HS_STRIDE + n0]           = fmaxf(acc[mi][ni][0] + bb0, 0.f);
                Hs[r0 * HS_STRIDE + n0 + 1]       = fmaxf(acc[mi][ni][1] + bb1, 0.f);
                Hs[(r0 + 8) * HS_STRIDE + n0]     = fmaxf(acc[mi][ni][2] + bb0, 0.f);
                Hs[(r0 + 8) * HS_STRIDE + n0 + 1] = fmaxf(acc[mi][ni][3] + bb1, 0.f);
                acc[mi][ni][0] = acc[mi][ni][1] = acc[mi][ni][2] = acc[mi][ni][3] = 0.f;
            }
        }
        const float* W3 = p.w3[gi] + (size_t)ki * 128 * 64;
        #pragma unroll
        for (int i = 0; i < 8; ++i) {
            int t = tid + i * 256;
            int r = t >> 4, q = (t & 15) << 2;
            *(float4*)(Ws + r * WS_STRIDE + q) = *(const float4*)(W3 + r * 64 + q);
        }
    }
    __syncthreads();

    // ======================= Layer 3: Out = H2*W3 + b3 ======================
    // warp grid: 4 (M, 32 rows each) x 2 (N, 32 cols each)
    const int wm3 = w & 3;
    const int wn3 = w >> 2;
    #pragma unroll 4
    for (int ks = 0; ks < 16; ++ks) {
        int k0 = ks * 8;
        uint32_t a[2][4];
        #pragma unroll
        for (int mi = 0; mi < 2; ++mi) {
            int r0 = wm3 * 32 + mi * 16;
            a[mi][0] = f2tf(Hs[(r0 + g)     * HS_STRIDE + k0 + t4]);
            a[mi][1] = f2tf(Hs[(r0 + g + 8) * HS_STRIDE + k0 + t4]);
            a[mi][2] = f2tf(Hs[(r0 + g)     * HS_STRIDE + k0 + t4 + 4]);
            a[mi][3] = f2tf(Hs[(r0 + g + 8) * HS_STRIDE + k0 + t4 + 4]);
        }
        #pragma unroll
        for (int ni = 0; ni < 4; ++ni) {
            int n0 = wn3 * 32 + ni * 8;
            uint32_t b0 = f2tf(Ws[(k0 + t4)     * WS_STRIDE + n0 + g]);
            uint32_t b1 = f2tf(Ws[(k0 + t4 + 4) * WS_STRIDE + n0 + g]);
            #pragma unroll
            for (int mi = 0; mi < 2; ++mi)
                mma8(acc[mi][ni], a[mi][0], a[mi][1], a[mi][2], a[mi][3], b0, b1);
        }
    }

    // epilogue 3: bias, store directly to gmem
    {
        const float* bp = p.b3[gi] + ki * 64;
        const int oj = c_out[node] * 64;
        #pragma unroll
        for (int ni = 0; ni < 4; ++ni) {
            int n0 = wn3 * 32 + ni * 8 + 2 * t4;
            float bb0 = bp[n0], bb1 = bp[n0 + 1];
            #pragma unroll
            for (int mi = 0; mi < 2; ++mi) {
                int r0 = m0 + wm3 * 32 + mi * 16 + g;
                float2 v0 = make_float2(acc[mi][ni][0] + bb0, acc[mi][ni][1] + bb1);
                float2 v1 = make_float2(acc[mi][ni][2] + bb0, acc[mi][ni][3] + bb1);
                *(float2*)(p.out + (size_t)r0 * 1344 + oj + n0)       = v0;
                *(float2*)(p.out + (size_t)(r0 + 8) * 1344 + oj + n0) = v1;
            }
        }
    }
}

extern "C" void kernel_launch(void* const* d_in, const int* in_sizes, int n_in,
                              void* d_out, int out_size) {
    (void)n_in; (void)out_size;
    Params p;
    p.x = (const float*)d_in[0];
    int idx = 1;
    for (int gi = 0; gi < 5; ++gi) {
        p.w1[gi] = (const float*)d_in[idx++];
        p.b1[gi] = (const float*)d_in[idx++];
        p.w2[gi] = (const float*)d_in[idx++];
        p.b2[gi] = (const float*)d_in[idx++];
        p.w3[gi] = (const float*)d_in[idx++];
        p.b3[gi] = (const float*)d_in[idx++];
    }
    p.out = (float*)d_out;

    const int B = in_sizes[0] / (21 * 64);

    cudaFuncSetAttribute(mp_kernel, cudaFuncAttributeMaxDynamicSharedMemorySize,
                         SMEM_BYTES);

    dim3 grid(21, B / 128);
    mp_kernel<<<grid, 256, SMEM_BYTES>>>(p);
}

// round 3
// speedup vs baseline: 1.0322x; 1.0322x over previous
#include <cuda_runtime.h>
#include <cstdint>

// ---------------------------------------------------------------------------
// Round 3: mma.sync tf32 with pair-major SMEM operand layouts.
//  - A-operand (X/H) pair-major: fragment = one LDS.64, conflict-free.
//  - B-operand (W) pre-transposed + pre-rounded + pre-shuffled by prep kernel
//    into the exact SMEM byte image -> kernel W load is a cp.async memcpy.
//  - M-tile 64 x 1 node, 256 thr, SMEM 85.5KB -> 2 CTAs/SM.
// ---------------------------------------------------------------------------

struct Params {
    const float* x;
    const float* w1[5]; const float* b1[5];
    const float* w2[5]; const float* b2[5];
    const float* w3[5]; const float* b3[5];
    float* out;
};

__constant__ int c_gi[21]  = {0,1,1,1,2,2,3,3,3,3,3,3,3,3,3,3,4,4,4,4,4};
__constant__ int c_ki[21]  = {0,0,1,2,0,1,0,1,2,3,4,5,6,7,8,9,0,1,2,3,4};
__constant__ int c_n[21]   = {6,5,5,5,4,4,3,3,3,3,3,3,3,3,3,3,2,2,2,2,2};
__constant__ int c_out[21] = {0,5,9,13,1,17,2,3,6,7,10,11,14,15,18,19,4,8,12,16,20};
__constant__ int c_nb[21][6] = {
    {0,1,5,9,13,17},
    {0,5,6,1,9,0},  {0,9,10,5,13,0}, {0,13,14,9,17,0},
    {0,1,2,5,0,0},  {0,17,18,13,0,0},
    {1,2,3,0,0,0},  {2,3,4,0,0,0},
    {5,6,7,0,0,0},  {6,7,8,0,0,0},
    {9,10,11,0,0,0},{10,11,12,0,0,0},
    {13,14,15,0,0,0},{14,15,16,0,0,0},
    {17,18,19,0,0,0},{18,19,20,0,0,0},
    {3,4,0,0,0,0},  {7,8,0,0,0,0}, {11,12,0,0,0,0},
    {15,16,0,0,0,0},{19,20,0,0,0,0}
};
// float offset of each node's W1 image (chunks of 8704 floats = one 64-k slab)
__constant__ int c_w1i_off[21] = {
    0,52224,95744,139264,182784,217600,
    252416,278528,304640,330752,356864,382976,409088,435200,461312,487424,
    513536,530944,548352,565760,583168
};

// Pre-shuffled weight images (exact SMEM byte layout incl. swizzle + padding)
__device__ __align__(16) float g_w1i[600576];
__device__ __align__(16) float g_w2i[365568];   // 21 * 2 chunks * 8704
__device__ __align__(16) float g_w3i[182784];   // 21 * 8704

// SMEM map (bytes). A-tiles 528B (16 rows*32B + 16B pad), B-tiles 272B.
#define SM_HA 0            // 4R * 16K8 tiles = 64*528  = 33792
#define SM_XA 33792        // 4R *  8K8 tiles = 32*528  = 16896
#define SM_WB 50688        // 16NB * 8K8 (or 8NB*16K8)  = 128*272 = 34816
#define SMEM_TOTAL 85504

__device__ __forceinline__ float tf32r(float f) {
    uint32_t r;
    asm("cvt.rna.tf32.f32 %0, %1;" : "=r"(r) : "f"(f));
    return __uint_as_float(r);
}
__device__ __forceinline__ uint32_t fu(float f) { return __float_as_uint(f); }

__device__ __forceinline__ void mma8(float c[4],
                                     uint32_t a0, uint32_t a1, uint32_t a2, uint32_t a3,
                                     uint32_t b0, uint32_t b1) {
    asm volatile(
        "mma.sync.aligned.m16n8k8.row.col.f32.tf32.tf32.f32 "
        "{%0,%1,%2,%3},{%4,%5,%6,%7},{%8,%9},{%0,%1,%2,%3};"
        : "+f"(c[0]), "+f"(c[1]), "+f"(c[2]), "+f"(c[3])
        : "r"(a0), "r"(a1), "r"(a2), "r"(a3), "r"(b0), "r"(b1));
}
__device__ __forceinline__ void domma(float c[4], float2 arg, float2 arg8, float2 b) {
    mma8(c, fu(arg.x), fu(arg8.x), fu(arg.y), fu(arg8.y), fu(b.x), fu(b.y));
}

#define CP16(dst, src) \
    asm volatile("cp.async.ca.shared.global [%0], [%1], 16;" :: "r"(dst), "l"(src))
#define CP_WAIT() \
    asm volatile("cp.async.commit_group;\ncp.async.wait_group 0;" ::: "memory")

__device__ __forceinline__ uint32_t smem_u32(const void* p) {
    uint32_t a;
    asm("{ .reg .u64 t; cvta.to.shared.u64 t, %1; cvt.u32.u64 %0, t; }"
        : "=r"(a) : "l"(p));
    return a;
}

// ------------------------------ prep kernel --------------------------------
// Writes W images: value tf32-rounded, layout = final SMEM image.
// Element (n-col of output, k): chunk c=k>>6 (w1/w2), K8=(k>>3) within chunk,
// kk=k&7, t4=kk&3, half=kk>>2, rn=n&7, NB=n>>3, s=(rn>>2)&1.
// off_in_chunk (floats) = (NB*NK8c + K8)*68 + rn*8 + ((t4>>1)^s)*4 + (t4&1)*2 + half
__device__ __forceinline__ int img_off(int n, int kk8, int K8, int NK8c) {
    int t4 = kk8 & 3, half = kk8 >> 2;
    int rn = n & 7, NB = n >> 3, s = (rn >> 2) & 1;
    return (NB * NK8c + K8) * 68 + rn * 8 + (((t4 >> 1) ^ s) << 2) + ((t4 & 1) << 1) + half;
}

__global__ void prep_kernel(Params p) {
    const int node = blockIdx.y;
    const int gi = c_gi[node], ki = c_ki[node], nnb = c_n[node];
    const int i = blockIdx.x * 256 + threadIdx.x;
    if (blockIdx.z == 0) {
        const int K1 = nnb * 64;
        if (i >= 128 * K1) return;
        const int k = i >> 7, n = i & 127;
        float v = tf32r(p.w1[gi][((size_t)ki * K1 + k) * 128 + n]);
        g_w1i[c_w1i_off[node] + (k >> 6) * 8704 + img_off(n, k & 7, (k >> 3) & 7, 8)] = v;
    } else if (blockIdx.z == 1) {
        if (i >= 16384) return;
        const int k = i >> 7, n = i & 127;
        float v = tf32r(p.w2[gi][(size_t)ki * 16384 + (size_t)k * 128 + n]);
        g_w2i[node * 17408 + (k >> 6) * 8704 + img_off(n, k & 7, (k >> 3) & 7, 8)] = v;
    } else {
        if (i >= 8192) return;
        const int k = i >> 6, n = i & 63;
        float v = tf32r(p.w3[gi][(size_t)ki * 8192 + (size_t)k * 64 + n]);
        g_w3i[node * 8704 + img_off(n, k & 7, k >> 3, 16)] = v;
    }
}

// ------------------------------ main kernel --------------------------------

__global__ __launch_bounds__(256, 2)
void mp3_kernel(Params p) {
    extern __shared__ char smem[];
    const int tid = threadIdx.x;
    const int w = tid >> 5, lane = tid & 31;
    const int g = lane >> 2, t4 = lane & 3;
    const int node = blockIdx.x;
    const int m0 = blockIdx.y * 64;
    const int gi = c_gi[node], ki = c_ki[node], nnb = c_n[node];
    const int wm = w & 1, wn = w >> 1;          // layers 1-2: 2M x 4N
    const int sg = (g >> 2) & 1;
    // pair-fragment lane offset (same formula for A reads and B reads)
    const int aoff = g * 32 + (((t4 >> 1) ^ sg) << 4) + ((t4 & 1) << 3);
    // epilogue store offsets (see derivation): p0 for even col, p0+8 for odd
    const int ep0 = (((t4 & 1) ^ sg) << 4) + ((t4 >> 1) << 2);

    const uint32_t sbWB = smem_u32(smem + SM_WB);

    float acc[2][4][4];
    #pragma unroll
    for (int mi = 0; mi < 2; ++mi)
        #pragma unroll
        for (int ni = 0; ni < 4; ++ni)
            #pragma unroll
            for (int r = 0; r < 4; ++r) acc[mi][ni][r] = 0.f;

    // ============================ Layer 1 ================================
    const float* w1i = g_w1i + c_w1i_off[node];
    #pragma unroll 1
    for (int c = 0; c < nnb; ++c) {
        if (c) __syncthreads();
        // W chunk: straight memcpy of the pre-built image (8704 floats)
        {
            const float* ws = w1i + c * 8704;
            #pragma unroll
            for (int i = 0; i < 8; ++i) {
                int idx = tid + i * 256;
                CP16(sbWB + idx * 16, ws + idx * 4);
            }
            if (tid < 128) CP16(sbWB + (2048 + tid) * 16, ws + (2048 + tid) * 4);
        }
        // X chunk: LDG -> tf32 round -> pair-shuffled STS.128 x2
        {
            const int jo = c_nb[node][c] * 64;
            const float* xb = p.x + (size_t)m0 * 1344 + jo;
            #pragma unroll
            for (int i = 0; i < 2; ++i) {
                int v = tid + i * 256;
                int m = v >> 3, K8 = v & 7;
                const float* s = xb + (size_t)m * 1344 + K8 * 8;
                float4 u = *(const float4*)s;
                float4 t = *(const float4*)(s + 4);
                int r = m & 15, R = m >> 4;
                char* dst = smem + SM_XA + (R * 8 + K8) * 528 + r * 32;
                int sw = (r & 4) << 2;
                float4 q0 = make_float4(tf32r(u.x), tf32r(t.x), tf32r(u.y), tf32r(t.y));
                float4 q1 = make_float4(tf32r(u.z), tf32r(t.z), tf32r(u.w), tf32r(t.w));
                *(float4*)(dst + sw) = q0;
                *(float4*)(dst + (16 ^ sw)) = q1;
            }
        }
        CP_WAIT();
        __syncthreads();
        #pragma unroll 4
        for (int k8 = 0; k8 < 8; ++k8) {
            float2 a[2][2];
            #pragma unroll
            for (int mi = 0; mi < 2; ++mi) {
                const char* ap = smem + SM_XA + ((wm * 2 + mi) * 8 + k8) * 528 + aoff;
                a[mi][0] = *(const float2*)ap;
                a[mi][1] = *(const float2*)(ap + 256);
            }
            #pragma unroll
            for (int ni = 0; ni < 4; ++ni) {
                const char* bp = smem + SM_WB + ((wn * 4 + ni) * 8 + k8) * 272 + aoff;
                float2 b = *(const float2*)bp;
                domma(acc[0][ni], a[0][0], a[0][1], b);
                domma(acc[1][ni], a[1][0], a[1][1], b);
            }
        }
    }

    // epilogue 1: bias + relu + round -> HA (pair-major scatter)
    {
        const float* bp = p.b1[gi] + ki * 128;
        #pragma unroll
        for (int ni = 0; ni < 4; ++ni) {
            int col0 = wn * 32 + ni * 8 + 2 * t4;
            float2 bb = *(const float2*)(bp + col0);
            int K8h = wn * 4 + ni;
            #pragma unroll
            for (int mi = 0; mi < 2; ++mi) {
                char* base = smem + SM_HA + ((wm * 2 + mi) * 16 + K8h) * 528 + g * 32;
                *(float*)(base + ep0)           = tf32r(fmaxf(acc[mi][ni][0] + bb.x, 0.f));
                *(float*)(base + ep0 + 8)       = tf32r(fmaxf(acc[mi][ni][1] + bb.y, 0.f));
                *(float*)(base + 256 + ep0)     = tf32r(fmaxf(acc[mi][ni][2] + bb.x, 0.f));
                *(float*)(base + 256 + ep0 + 8) = tf32r(fmaxf(acc[mi][ni][3] + bb.y, 0.f));
                acc[mi][ni][0] = acc[mi][ni][1] = acc[mi][ni][2] = acc[mi][ni][3] = 0.f;
            }
        }
    }
    __syncthreads();

    // ============================ Layer 2 ================================
    const float* w2i = g_w2i + node * 17408;
    #pragma unroll 1
    for (int c = 0; c < 2; ++c) {
        if (c) __syncthreads();
        {
            const float* ws = w2i + c * 8704;
            #pragma unroll
            for (int i = 0; i < 8; ++i) {
                int idx = tid + i * 256;
                CP16(sbWB + idx * 16, ws + idx * 4);
            }
            if (tid < 128) CP16(sbWB + (2048 + tid) * 16, ws + (2048 + tid) * 4);
        }
        CP_WAIT();
        __syncthreads();
        #pragma unroll 4
        for (int k8 = 0; k8 < 8; ++k8) {
            float2 a[2][2];
            #pragma unroll
            for (int mi = 0; mi < 2; ++mi) {
                const char* ap = smem + SM_HA +
                    ((wm * 2 + mi) * 16 + c * 8 + k8) * 528 + aoff;
                a[mi][0] = *(const float2*)ap;
                a[mi][1] = *(const float2*)(ap + 256);
            }
            #pragma unroll
            for (int ni = 0; ni < 4; ++ni) {
                const char* bp = smem + SM_WB + ((wn * 4 + ni) * 8 + k8) * 272 + aoff;
                float2 b = *(const float2*)bp;
                domma(acc[0][ni], a[0][0], a[0][1], b);
                domma(acc[1][ni], a[1][0], a[1][1], b);
            }
        }
    }
    __syncthreads();   // all layer-2 reads of HA done before in-place overwrite

    // epilogue 2: bias + relu + round -> HA (in place)
    {
        const float* bp = p.b2[gi] + ki * 128;
        #pragma unroll
        for (int ni = 0; ni < 4; ++ni) {
            int col0 = wn * 32 + ni * 8 + 2 * t4;
            float2 bb = *(const float2*)(bp + col0);
            int K8h = wn * 4 + ni;
            #pragma unroll
            for (int mi = 0; mi < 2; ++mi) {
                char* base = smem + SM_HA + ((wm * 2 + mi) * 16 + K8h) * 528 + g * 32;
                *(float*)(base + ep0)           = tf32r(fmaxf(acc[mi][ni][0] + bb.x, 0.f));
                *(float*)(base + ep0 + 8)       = tf32r(fmaxf(acc[mi][ni][1] + bb.y, 0.f));
                *(float*)(base + 256 + ep0)     = tf32r(fmaxf(acc[mi][ni][2] + bb.x, 0.f));
                *(float*)(base + 256 + ep0 + 8) = tf32r(fmaxf(acc[mi][ni][3] + bb.y, 0.f));
                acc[mi][ni][0] = acc[mi][ni][1] = acc[mi][ni][2] = acc[mi][ni][3] = 0.f;
            }
        }
    }
    __syncthreads();

    // ============================ Layer 3 ================================
    // warp grid: 4M x 2N; B image NK8=16
    {
        const float* ws = g_w3i + node * 8704;
        #pragma unroll
        for (int i = 0; i < 8; ++i) {
            int idx = tid + i * 256;
            CP16(sbWB + idx * 16, ws + idx * 4);
        }
        if (tid < 128) CP16(sbWB + (2048 + tid) * 16, ws + (2048 + tid) * 4);
    }
    CP_WAIT();
    __syncthreads();

    const int wm3 = w & 3, wn3 = w >> 2;
    #pragma unroll 4
    for (int k8 = 0; k8 < 16; ++k8) {
        const char* ap = smem + SM_HA + (wm3 * 16 + k8) * 528 + aoff;
        float2 a0 = *(const float2*)ap;
        float2 a1 = *(const float2*)(ap + 256);
        #pragma unroll
        for (int ni = 0; ni < 4; ++ni) {
            const char* bp = smem + SM_WB + ((wn3 * 4 + ni) * 16 + k8) * 272 + aoff;
            float2 b = *(const float2*)bp;
            domma(acc[0][ni], a0, a1, b);
        }
    }

    // epilogue 3: bias, STG.64 direct (coalesced 32B sectors)
    {
        const float* bp = p.b3[gi] + ki * 64;
        const int oj = c_out[node] * 64;
        #pragma unroll
        for (int ni = 0; ni < 4; ++ni) {
            int col0 = wn3 * 32 + ni * 8 + 2 * t4;
            float2 bb = *(const float2*)(bp + col0);
            size_t ro = (size_t)(m0 + wm3 * 16 + g) * 1344 + oj + col0;
            *(float2*)(p.out + ro) =
                make_float2(acc[0][ni][0] + bb.x, acc[0][ni][1] + bb.y);
            *(float2*)(p.out + ro + (size_t)8 * 1344) =
                make_float2(acc[0][ni][2] + bb.x, acc[0][ni][3] + bb.y);
        }
    }
}

// ------------------------------ launch -------------------------------------

extern "C" void kernel_launch(void* const* d_in, const int* in_sizes, int n_in,
                              void* d_out, int out_size) {
    (void)n_in; (void)out_size;
    Params p;
    p.x = (const float*)d_in[0];
    int idx = 1;
    for (int gi = 0; gi < 5; ++gi) {
        p.w1[gi] = (const float*)d_in[idx++];
        p.b1[gi] = (const float*)d_in[idx++];
        p.w2[gi] = (const float*)d_in[idx++];
        p.b2[gi] = (const float*)d_in[idx++];
        p.w3[gi] = (const float*)d_in[idx++];
        p.b3[gi] = (const float*)d_in[idx++];
    }
    p.out = (float*)d_out;

    const int B = in_sizes[0] / (21 * 64);

    prep_kernel<<<dim3(192, 21, 3), 256>>>(p);

    cudaFuncSetAttribute(mp3_kernel, cudaFuncAttributeMaxDynamicSharedMemorySize,
                         SMEM_TOTAL);
    dim3 grid(21, B / 64);
    mp3_kernel<<<grid, 256, SMEM_TOTAL>>>(p);
}

// round 4
// speedup vs baseline: 1.0543x; 1.0214x over previous
#include <cuda_runtime.h>
#include <cstdint>

// ---------------------------------------------------------------------------
// Round 4: mma.sync tf32, M_tile=256, warp tile 64x64 (4M x 2N warp grid).
//  - 1 CTA/SM, 231KB SMEM; weight cp.async amortized over 256 rows.
//  - Fragment replication minimized: 0.122 smem-B/MAC -> tensor-bound.
//  - Layout formulas identical to passing R3 (rel_err 1.82e-4).
// ---------------------------------------------------------------------------

struct Params {
    const float* x;
    const float* w1[5]; const float* b1[5];
    const float* w2[5]; const float* b2[5];
    const float* w3[5]; const float* b3[5];
    float* out;
};

__constant__ int c_gi[21]  = {0,1,1,1,2,2,3,3,3,3,3,3,3,3,3,3,4,4,4,4,4};
__constant__ int c_ki[21]  = {0,0,1,2,0,1,0,1,2,3,4,5,6,7,8,9,0,1,2,3,4};
__constant__ int c_n[21]   = {6,5,5,5,4,4,3,3,3,3,3,3,3,3,3,3,2,2,2,2,2};
__constant__ int c_out[21] = {0,5,9,13,1,17,2,3,6,7,10,11,14,15,18,19,4,8,12,16,20};
__constant__ int c_nb[21][6] = {
    {0,1,5,9,13,17},
    {0,5,6,1,9,0},  {0,9,10,5,13,0}, {0,13,14,9,17,0},
    {0,1,2,5,0,0},  {0,17,18,13,0,0},
    {1,2,3,0,0,0},  {2,3,4,0,0,0},
    {5,6,7,0,0,0},  {6,7,8,0,0,0},
    {9,10,11,0,0,0},{10,11,12,0,0,0},
    {13,14,15,0,0,0},{14,15,16,0,0,0},
    {17,18,19,0,0,0},{18,19,20,0,0,0},
    {3,4,0,0,0,0},  {7,8,0,0,0,0}, {11,12,0,0,0,0},
    {15,16,0,0,0,0},{19,20,0,0,0,0}
};
// per-node float offset of W1 image (chunks of 8192 floats = one 64-k slab)
__constant__ int c_w1i_off[21] = {
    0,49152,90112,131072,172032,204800,
    237568,262144,286720,311296,335872,360448,385024,409600,434176,458752,
    483328,499712,516096,532480,548864
};

// Pre-shuffled, tf32-rounded weight images (exact SMEM byte layout)
__device__ __align__(16) float g_w1i[565248];
__device__ __align__(16) float g_w2i[344064];   // 21 * 2 * 8192
__device__ __align__(16) float g_w3i[172032];   // 21 * 8192

// SMEM map (bytes). HA tiles 512B, XA tiles 528B (16B pad for X-store), WB 256B.
#define SM_HA 0                      // 16R * 16K8 * 512 = 131072
#define SM_XA 131072                 // 16R *  8K8 * 528 =  67584
#define SM_WB 198656                 // 16NB * 8K8 * 256 =  32768 (or 8NB*16K8)
#define SMEM_TOTAL 231424

__device__ __forceinline__ float tf32r(float f) {
    uint32_t r;
    asm("cvt.rna.tf32.f32 %0, %1;" : "=r"(r) : "f"(f));
    return __uint_as_float(r);
}
__device__ __forceinline__ uint32_t fu(float f) { return __float_as_uint(f); }

__device__ __forceinline__ void mma8(float c[4],
                                     uint32_t a0, uint32_t a1, uint32_t a2, uint32_t a3,
                                     uint32_t b0, uint32_t b1) {
    asm volatile(
        "mma.sync.aligned.m16n8k8.row.col.f32.tf32.tf32.f32 "
        "{%0,%1,%2,%3},{%4,%5,%6,%7},{%8,%9},{%0,%1,%2,%3};"
        : "+f"(c[0]), "+f"(c[1]), "+f"(c[2]), "+f"(c[3])
        : "r"(a0), "r"(a1), "r"(a2), "r"(a3), "r"(b0), "r"(b1));
}
__device__ __forceinline__ void domma(float c[4], float2 a, float2 a8, float2 b) {
    mma8(c, fu(a.x), fu(a8.x), fu(a.y), fu(a8.y), fu(b.x), fu(b.y));
}

#define CP16(dst, src) \
    asm volatile("cp.async.ca.shared.global [%0], [%1], 16;" :: "r"(dst), "l"(src))
#define CP_WAIT() \
    asm volatile("cp.async.commit_group;\ncp.async.wait_group 0;" ::: "memory")

__device__ __forceinline__ uint32_t smem_u32(const void* p) {
    uint32_t a;
    asm("{ .reg .u64 t; cvta.to.shared.u64 t, %1; cvt.u32.u64 %0, t; }"
        : "=r"(a) : "l"(p));
    return a;
}

// ------------------------------ prep kernel --------------------------------
// W image element (n = output col, k): K8 index within chunk, kk=k&7.
// off (floats) = (NB*NK8c + K8)*64 + rn*8 + ((t4>>1)^s)*4 + (t4&1)*2 + half
__device__ __forceinline__ int img_off(int n, int kk8, int K8, int NK8c) {
    int t4 = kk8 & 3, half = kk8 >> 2;
    int rn = n & 7, NB = n >> 3, s = (rn >> 2) & 1;
    return (NB * NK8c + K8) * 64 + rn * 8 + (((t4 >> 1) ^ s) << 2) + ((t4 & 1) << 1) + half;
}

__global__ void prep_kernel(Params p) {
    const int node = blockIdx.y;
    const int gi = c_gi[node], ki = c_ki[node], nnb = c_n[node];
    const int i = blockIdx.x * 256 + threadIdx.x;
    if (blockIdx.z == 0) {
        const int K1 = nnb * 64;
        if (i >= 128 * K1) return;
        const int k = i >> 7, n = i & 127;
        float v = tf32r(p.w1[gi][((size_t)ki * K1 + k) * 128 + n]);
        g_w1i[c_w1i_off[node] + (k >> 6) * 8192 + img_off(n, k & 7, (k >> 3) & 7, 8)] = v;
    } else if (blockIdx.z == 1) {
        if (i >= 16384) return;
        const int k = i >> 7, n = i & 127;
        float v = tf32r(p.w2[gi][(size_t)ki * 16384 + (size_t)k * 128 + n]);
        g_w2i[node * 16384 + (k >> 6) * 8192 + img_off(n, k & 7, (k >> 3) & 7, 8)] = v;
    } else {
        if (i >= 8192) return;
        const int k = i >> 6, n = i & 63;
        float v = tf32r(p.w3[gi][(size_t)ki * 8192 + (size_t)k * 64 + n]);
        g_w3i[node * 8192 + img_off(n, k & 7, k >> 3, 16)] = v;
    }
}

// ------------------------------ main kernel --------------------------------

__global__ __launch_bounds__(256)
void mp4_kernel(Params p) {
    extern __shared__ char smem[];
    const int tid = threadIdx.x;
    const int w = tid >> 5, lane = tid & 31;
    const int g = lane >> 2, t4 = lane & 3;
    const int node = blockIdx.x;
    const int m0 = blockIdx.y * 256;
    const int gi = c_gi[node], ki = c_ki[node], nnb = c_n[node];
    const int wm = w & 3, wn = w >> 2;          // 4M x 2N warp grid
    const int sg = (g >> 2) & 1;
    const int aoff = g * 32 + (((t4 >> 1) ^ sg) << 4) + ((t4 & 1) << 3);
    const int ep0  = (((t4 & 1) ^ sg) << 4) + ((t4 >> 1) << 2);

    const uint32_t sbWB = smem_u32(smem + SM_WB);

    float acc[4][8][4];
    #pragma unroll
    for (int mi = 0; mi < 4; ++mi)
        #pragma unroll
        for (int ni = 0; ni < 8; ++ni)
            #pragma unroll
            for (int r = 0; r < 4; ++r) acc[mi][ni][r] = 0.f;

    // ============================ Layer 1 ================================
    const float* w1i = g_w1i + c_w1i_off[node];
    #pragma unroll 1
    for (int c = 0; c < nnb; ++c) {
        if (c) __syncthreads();
        {   // W chunk memcpy (8192 floats)
            const float* ws = w1i + c * 8192;
            #pragma unroll
            for (int i = 0; i < 8; ++i) {
                int idx = tid + i * 256;
                CP16(sbWB + idx * 16, ws + idx * 4);
            }
        }
        {   // X chunk: 256 rows x 64 cols, LDG -> tf32 -> pair-shuffled STS.128
            const int jo = c_nb[node][c] * 64;
            const float* xb = p.x + (size_t)m0 * 1344 + jo;
            #pragma unroll
            for (int i = 0; i < 8; ++i) {
                int v = tid + i * 256;
                int m = v >> 3, K8 = v & 7;
                const float* s = xb + (size_t)m * 1344 + K8 * 8;
                float4 u = *(const float4*)s;
                float4 t = *(const float4*)(s + 4);
                int r = m & 15, R = m >> 4;
                char* dst = smem + SM_XA + (R * 8 + K8) * 528 + r * 32;
                int sw = (r & 4) << 2;
                float4 q0 = make_float4(tf32r(u.x), tf32r(t.x), tf32r(u.y), tf32r(t.y));
                float4 q1 = make_float4(tf32r(u.z), tf32r(t.z), tf32r(u.w), tf32r(t.w));
                *(float4*)(dst + sw) = q0;
                *(float4*)(dst + (16 ^ sw)) = q1;
            }
        }
        CP_WAIT();
        __syncthreads();
        #pragma unroll 2
        for (int k8 = 0; k8 < 8; ++k8) {
            float2 a[4][2];
            #pragma unroll
            for (int mi = 0; mi < 4; ++mi) {
                const char* ap = smem + SM_XA + ((wm * 4 + mi) * 8 + k8) * 528 + aoff;
                a[mi][0] = *(const float2*)ap;
                a[mi][1] = *(const float2*)(ap + 256);
            }
            #pragma unroll
            for (int ni = 0; ni < 8; ++ni) {
                const char* bp = smem + SM_WB + ((wn * 8 + ni) * 8 + k8) * 256 + aoff;
                float2 b = *(const float2*)bp;
                #pragma unroll
                for (int mi = 0; mi < 4; ++mi)
                    domma(acc[mi][ni], a[mi][0], a[mi][1], b);
            }
        }
    }

    // epilogue 1: bias + relu + round -> HA (512B tiles)
    {
        const float* bp = p.b1[gi] + ki * 128;
        #pragma unroll
        for (int ni = 0; ni < 8; ++ni) {
            int col0 = wn * 64 + ni * 8 + 2 * t4;
            float2 bb = *(const float2*)(bp + col0);
            #pragma unroll
            for (int mi = 0; mi < 4; ++mi) {
                char* base = smem + SM_HA +
                    (((wm * 4 + mi) * 16) + wn * 8 + ni) * 512 + g * 32;
                *(float*)(base + ep0)           = tf32r(fmaxf(acc[mi][ni][0] + bb.x, 0.f));
                *(float*)(base + ep0 + 8)       = tf32r(fmaxf(acc[mi][ni][1] + bb.y, 0.f));
                *(float*)(base + 256 + ep0)     = tf32r(fmaxf(acc[mi][ni][2] + bb.x, 0.f));
                *(float*)(base + 256 + ep0 + 8) = tf32r(fmaxf(acc[mi][ni][3] + bb.y, 0.f));
                acc[mi][ni][0] = acc[mi][ni][1] = acc[mi][ni][2] = acc[mi][ni][3] = 0.f;
            }
        }
    }
    __syncthreads();

    // ============================ Layer 2 ================================
    const float* w2i = g_w2i + node * 16384;
    #pragma unroll 1
    for (int c = 0; c < 2; ++c) {
        if (c) __syncthreads();
        {
            const float* ws = w2i + c * 8192;
            #pragma unroll
            for (int i = 0; i < 8; ++i) {
                int idx = tid + i * 256;
                CP16(sbWB + idx * 16, ws + idx * 4);
            }
        }
        CP_WAIT();
        __syncthreads();
        #pragma unroll 2
        for (int k8 = 0; k8 < 8; ++k8) {
            float2 a[4][2];
            #pragma unroll
            for (int mi = 0; mi < 4; ++mi) {
                const char* ap = smem + SM_HA +
                    ((wm * 4 + mi) * 16 + c * 8 + k8) * 512 + aoff;
                a[mi][0] = *(const float2*)ap;
                a[mi][1] = *(const float2*)(ap + 256);
            }
            #pragma unroll
            for (int ni = 0; ni < 8; ++ni) {
                const char* bp = smem + SM_WB + ((wn * 8 + ni) * 8 + k8) * 256 + aoff;
                float2 b = *(const float2*)bp;
                #pragma unroll
                for (int mi = 0; mi < 4; ++mi)
                    domma(acc[mi][ni], a[mi][0], a[mi][1], b);
            }
        }
    }
    __syncthreads();   // all layer-2 HA reads complete before in-place overwrite

    // epilogue 2: bias + relu + round -> HA (in place)
    {
        const float* bp = p.b2[gi] + ki * 128;
        #pragma unroll
        for (int ni = 0; ni < 8; ++ni) {
            int col0 = wn * 64 + ni * 8 + 2 * t4;
            float2 bb = *(const float2*)(bp + col0);
            #pragma unroll
            for (int mi = 0; mi < 4; ++mi) {
                char* base = smem + SM_HA +
                    (((wm * 4 + mi) * 16) + wn * 8 + ni) * 512 + g * 32;
                *(float*)(base + ep0)           = tf32r(fmaxf(acc[mi][ni][0] + bb.x, 0.f));
                *(float*)(base + ep0 + 8)       = tf32r(fmaxf(acc[mi][ni][1] + bb.y, 0.f));
                *(float*)(base + 256 + ep0)     = tf32r(fmaxf(acc[mi][ni][2] + bb.x, 0.f));
                *(float*)(base + 256 + ep0 + 8) = tf32r(fmaxf(acc[mi][ni][3] + bb.y, 0.f));
                acc[mi][ni][0] = acc[mi][ni][1] = acc[mi][ni][2] = acc[mi][ni][3] = 0.f;
            }
        }
    }
    __syncthreads();

    // ============================ Layer 3 ================================
    {   // W3 image: 64n x 128k, NK8=16
        const float* ws = g_w3i + node * 8192;
        #pragma unroll
        for (int i = 0; i < 8; ++i) {
            int idx = tid + i * 256;
            CP16(sbWB + idx * 16, ws + idx * 4);
        }
    }
    CP_WAIT();
    __syncthreads();

    #pragma unroll 2
    for (int k8 = 0; k8 < 16; ++k8) {
        float2 a[4][2];
        #pragma unroll
        for (int mi = 0; mi < 4; ++mi) {
            const char* ap = smem + SM_HA + ((wm * 4 + mi) * 16 + k8) * 512 + aoff;
            a[mi][0] = *(const float2*)ap;
            a[mi][1] = *(const float2*)(ap + 256);
        }
        #pragma unroll
        for (int ni = 0; ni < 4; ++ni) {
            const char* bp = smem + SM_WB + ((wn * 4 + ni) * 16 + k8) * 256 + aoff;
            float2 b = *(const float2*)bp;
            #pragma unroll
            for (int mi = 0; mi < 4; ++mi)
                domma(acc[mi][ni], a[mi][0], a[mi][1], b);
        }
    }

    // epilogue 3: bias, STG.64 direct
    {
        const float* bp = p.b3[gi] + ki * 64;
        const int oj = c_out[node] * 64;
        #pragma unroll
        for (int ni = 0; ni < 4; ++ni) {
            int col0 = wn * 32 + ni * 8 + 2 * t4;
            float2 bb = *(const float2*)(bp + col0);
            #pragma unroll
            for (int mi = 0; mi < 4; ++mi) {
                size_t ro = (size_t)(m0 + wm * 64 + mi * 16 + g) * 1344 + oj + col0;
                *(float2*)(p.out + ro) =
                    make_float2(acc[mi][ni][0] + bb.x, acc[mi][ni][1] + bb.y);
                *(float2*)(p.out + ro + (size_t)8 * 1344) =
                    make_float2(acc[mi][ni][2] + bb.x, acc[mi][ni][3] + bb.y);
            }
        }
    }
}

// ------------------------------ launch -------------------------------------

extern "C" void kernel_launch(void* const* d_in, const int* in_sizes, int n_in,
                              void* d_out, int out_size) {
    (void)n_in; (void)out_size;
    Params p;
    p.x = (const float*)d_in[0];
    int idx = 1;
    for (int gi = 0; gi < 5; ++gi) {
        p.w1[gi] = (const float*)d_in[idx++];
        p.b1[gi] = (const float*)d_in[idx++];
        p.w2[gi] = (const float*)d_in[idx++];
        p.b2[gi] = (const float*)d_in[idx++];
        p.w3[gi] = (const float*)d_in[idx++];
        p.b3[gi] = (const float*)d_in[idx++];
    }
    p.out = (float*)d_out;

    const int B = in_sizes[0] / (21 * 64);

    prep_kernel<<<dim3(192, 21, 3), 256>>>(p);

    cudaFuncSetAttribute(mp4_kernel, cudaFuncAttributeMaxDynamicSharedMemorySize,
                         SMEM_TOTAL);
    dim3 grid(21, B / 256);
    mp4_kernel<<<grid, 256, SMEM_TOTAL>>>(p);
}

// round 6
// speedup vs baseline: 1.9356x; 1.8358x over previous
#include <cuda_runtime.h>
#include <cuda_fp16.h>
#include <cstdint>

// ---------------------------------------------------------------------------
// Round 6: R5 (mma.sync m16n8k16 fp16, fp32 accum) with the prep-image tile
// stride bug fixed: B tile = 8 rows x 32B = 128 halves (was wrongly 256).
// M_tile=128, warp tile 32x64, 2 CTAs/SM (66KB smem each).
// ---------------------------------------------------------------------------

struct Params {
    const float* x;
    const float* w1[5]; const float* b1[5];
    const float* w2[5]; const float* b2[5];
    const float* w3[5]; const float* b3[5];
    float* out;
};

__constant__ int c_gi[21]  = {0,1,1,1,2,2,3,3,3,3,3,3,3,3,3,3,4,4,4,4,4};
__constant__ int c_ki[21]  = {0,0,1,2,0,1,0,1,2,3,4,5,6,7,8,9,0,1,2,3,4};
__constant__ int c_n[21]   = {6,5,5,5,4,4,3,3,3,3,3,3,3,3,3,3,2,2,2,2,2};
__constant__ int c_out[21] = {0,5,9,13,1,17,2,3,6,7,10,11,14,15,18,19,4,8,12,16,20};
__constant__ int c_nb[21][6] = {
    {0,1,5,9,13,17},
    {0,5,6,1,9,0},  {0,9,10,5,13,0}, {0,13,14,9,17,0},
    {0,1,2,5,0,0},  {0,17,18,13,0,0},
    {1,2,3,0,0,0},  {2,3,4,0,0,0},
    {5,6,7,0,0,0},  {6,7,8,0,0,0},
    {9,10,11,0,0,0},{10,11,12,0,0,0},
    {13,14,15,0,0,0},{14,15,16,0,0,0},
    {17,18,19,0,0,0},{18,19,20,0,0,0},
    {3,4,0,0,0,0},  {7,8,0,0,0,0}, {11,12,0,0,0,0},
    {15,16,0,0,0,0},{19,20,0,0,0,0}
};
// per-node half-offset of W1 image (chunks of 8192 halves = one 64-k slab)
__constant__ int c_w1i_off[21] = {
    0,49152,90112,131072,172032,204800,
    237568,262144,286720,311296,335872,360448,385024,409600,434176,458752,
    483328,499712,516096,532480,548864
};

// Pre-shuffled fp16 weight images (exact SMEM byte layout)
__device__ __align__(16) __half g_w1i[565248];
__device__ __align__(16) __half g_w2i[344064];   // 21 * 2 * 8192
__device__ __align__(16) __half g_w3i[172032];   // 21 * 8192

// SMEM map (bytes). Tiles: 16 rows x 32B. HA 512B, XA 528B (pad), WB 256B.
#define SM_HA 0                      // 8R * 8K16 * 512 = 32768
#define SM_XA 32768                  // 8R * 4K16 * 528 = 16896
#define SM_WB 49664                  // 16KB W chunk
#define SMEM_TOTAL 66048

__device__ __forceinline__ uint32_t pkh2(float lo, float hi) {
    uint32_t r;   // cvt.rn.f16x2.f32 d, hi, lo  -> low half = lo
    asm("cvt.rn.f16x2.f32 %0, %1, %2;" : "=r"(r) : "f"(hi), "f"(lo));
    return r;
}

__device__ __forceinline__ void mma16(float c[4],
                                      uint32_t a0, uint32_t a1, uint32_t a2, uint32_t a3,
                                      uint32_t b0, uint32_t b1) {
    asm volatile(
        "mma.sync.aligned.m16n8k16.row.col.f32.f16.f16.f32 "
        "{%0,%1,%2,%3},{%4,%5,%6,%7},{%8,%9},{%0,%1,%2,%3};"
        : "+f"(c[0]), "+f"(c[1]), "+f"(c[2]), "+f"(c[3])
        : "r"(a0), "r"(a1), "r"(a2), "r"(a3), "r"(b0), "r"(b1));
}
__device__ __forceinline__ void domma(float c[4], uint2 Pg, uint2 Pg8, uint2 Pb) {
    mma16(c, Pg.x, Pg8.x, Pg.y, Pg8.y, Pb.x, Pb.y);
}

#define CP16(dst, src) \
    asm volatile("cp.async.ca.shared.global [%0], [%1], 16;" :: "r"(dst), "l"(src))
#define CP_WAIT() \
    asm volatile("cp.async.commit_group;\ncp.async.wait_group 0;" ::: "memory")

__device__ __forceinline__ uint32_t smem_u32(const void* p) {
    uint32_t a;
    asm("{ .reg .u64 t; cvta.to.shared.u64 t, %1; cvt.u32.u64 %0, t; }"
        : "=r"(a) : "l"(p));
    return a;
}

// ------------------------------ prep kernel --------------------------------
// Image half-offset of element (n = output col, k) within a chunk.
// Tile = (n>>3)*NK16c + local k16; tile stride = 128 HALVES (8 rows x 16).
// Row rn = n&7; within row: halfidx = (((k>>2)&1)^s)<<3 | ((k>>1)&1)<<2
//                                     | ((k>>3)&1)<<1 | (k&1), s=(rn>>2)&1.
__device__ __forceinline__ int imgh(int n, int k, int K16, int NK16c) {
    int jw = (k & 15) >> 1, lo = k & 1;
    int rn = n & 7, NB = n >> 3, s = (rn >> 2) & 1;
    return (NB * NK16c + K16) * 128 + rn * 16 +
           ((((jw >> 1) & 1) ^ s) << 3) + ((jw & 1) << 2) + ((jw >> 2) << 1) + lo;
}

__global__ void prep_kernel(Params p) {
    const int node = blockIdx.y;
    const int gi = c_gi[node], ki = c_ki[node], nnb = c_n[node];
    const int i = blockIdx.x * 256 + threadIdx.x;
    if (blockIdx.z == 0) {
        const int K1 = nnb * 64;
        if (i >= 128 * K1) return;
        const int k = i >> 7, n = i & 127;
        float v = p.w1[gi][((size_t)ki * K1 + k) * 128 + n];
        g_w1i[c_w1i_off[node] + (k >> 6) * 8192 + imgh(n, k, (k >> 4) & 3, 4)] =
            __float2half_rn(v);
    } else if (blockIdx.z == 1) {
        if (i >= 16384) return;
        const int k = i >> 7, n = i & 127;
        float v = p.w2[gi][(size_t)ki * 16384 + (size_t)k * 128 + n];
        g_w2i[node * 16384 + (k >> 6) * 8192 + imgh(n, k, (k >> 4) & 3, 4)] =
            __float2half_rn(v);
    } else {
        if (i >= 8192) return;
        const int k = i >> 6, n = i & 63;
        float v = p.w3[gi][(size_t)ki * 8192 + (size_t)k * 64 + n];
        g_w3i[node * 8192 + imgh(n, k, k >> 4, 8)] = __float2half_rn(v);
    }
}

// ------------------------------ main kernel --------------------------------

__global__ __launch_bounds__(256, 2)
void mp6_kernel(Params p) {
    extern __shared__ char smem[];
    const int tid = threadIdx.x;
    const int w = tid >> 5, lane = tid & 31;
    const int g = lane >> 2, t4 = lane & 3;
    const int node = blockIdx.x;
    const int m0 = blockIdx.y * 128;
    const int gi = c_gi[node], ki = c_ki[node], nnb = c_n[node];
    const int wm = w & 3, wn = w >> 2;          // 4M x 2N warp grid (32x64 tiles)
    const int sg = (g >> 2) & 1;
    const int aoff = g * 32 + (((t4 >> 1) ^ sg) << 4) + ((t4 & 1) << 3);
    const int awl  = (((t4 >> 1) ^ sg) << 4) + ((t4 & 1) << 3);  // lane word off

    const uint32_t sbWB = smem_u32(smem + SM_WB);

    float acc[2][8][4];
    #pragma unroll
    for (int mi = 0; mi < 2; ++mi)
        #pragma unroll
        for (int ni = 0; ni < 8; ++ni)
            #pragma unroll
            for (int r = 0; r < 4; ++r) acc[mi][ni][r] = 0.f;

    // ============================ Layer 1 ================================
    const __half* w1i = g_w1i + c_w1i_off[node];
    #pragma unroll 1
    for (int c = 0; c < nnb; ++c) {
        if (c) __syncthreads();
        {   // W chunk image memcpy: 8192 halves = 16KB
            const __half* ws = w1i + c * 8192;
            #pragma unroll
            for (int i = 0; i < 4; ++i) {
                int idx = tid + i * 256;
                CP16(sbWB + idx * 16, ws + idx * 8);
            }
        }
        {   // X chunk: 128 rows x 64 cols f32 -> f16 pair-shuffled
            const int jo = c_nb[node][c] * 64;
            const float* xb = p.x + (size_t)m0 * 1344 + jo;
            #pragma unroll
            for (int i = 0; i < 2; ++i) {
                int v = tid + i * 256;
                int m = v >> 2, kt = v & 3;
                const float* s = xb + (size_t)m * 1344 + kt * 16;
                float4 A0 = *(const float4*)s;
                float4 A1 = *(const float4*)(s + 4);
                float4 A2 = *(const float4*)(s + 8);
                float4 A3 = *(const float4*)(s + 12);
                uint4 q0 = make_uint4(pkh2(A0.x, A0.y), pkh2(A2.x, A2.y),
                                      pkh2(A0.z, A0.w), pkh2(A2.z, A2.w));
                uint4 q1 = make_uint4(pkh2(A1.x, A1.y), pkh2(A3.x, A3.y),
                                      pkh2(A1.z, A1.w), pkh2(A3.z, A3.w));
                int r = m & 15, R = m >> 4;
                char* dst = smem + SM_XA + (R * 4 + kt) * 528 + r * 32;
                int sw = (r & 4) << 2;
                *(uint4*)(dst + sw) = q0;
                *(uint4*)(dst + (16 ^ sw)) = q1;
            }
        }
        CP_WAIT();
        __syncthreads();
        #pragma unroll
        for (int k16 = 0; k16 < 4; ++k16) {
            uint2 a[2][2];
            #pragma unroll
            for (int mi = 0; mi < 2; ++mi) {
                const char* ap = smem + SM_XA + ((wm * 2 + mi) * 4 + k16) * 528 + aoff;
                a[mi][0] = *(const uint2*)ap;
                a[mi][1] = *(const uint2*)(ap + 256);
            }
            #pragma unroll
            for (int ni = 0; ni < 8; ++ni) {
                const char* bp = smem + SM_WB + ((wn * 8 + ni) * 4 + k16) * 256 + aoff;
                uint2 b = *(const uint2*)bp;
                domma(acc[0][ni], a[0][0], a[0][1], b);
                domma(acc[1][ni], a[1][0], a[1][1], b);
            }
        }
    }

    // epilogue 1: bias + relu -> fp16 words into HA
    {
        const float* bp = p.b1[gi] + ki * 128;
        #pragma unroll
        for (int ni = 0; ni < 8; ++ni) {
            int col0 = wn * 64 + ni * 8 + 2 * t4;
            float2 bb = *(const float2*)(bp + col0);
            int kt = wn * 4 + (ni >> 1);
            int off = awl + ((ni & 1) << 2);
            #pragma unroll
            for (int mi = 0; mi < 2; ++mi) {
                char* base = smem + SM_HA + ((wm * 2 + mi) * 8 + kt) * 512 + g * 32 + off;
                *(uint32_t*)base = pkh2(fmaxf(acc[mi][ni][0] + bb.x, 0.f),
                                        fmaxf(acc[mi][ni][1] + bb.y, 0.f));
                *(uint32_t*)(base + 256) = pkh2(fmaxf(acc[mi][ni][2] + bb.x, 0.f),
                                                fmaxf(acc[mi][ni][3] + bb.y, 0.f));
                acc[mi][ni][0] = acc[mi][ni][1] = acc[mi][ni][2] = acc[mi][ni][3] = 0.f;
            }
        }
    }
    __syncthreads();

    // ============================ Layer 2 ================================
    const __half* w2i = g_w2i + node * 16384;
    #pragma unroll 1
    for (int c = 0; c < 2; ++c) {
        if (c) __syncthreads();
        {
            const __half* ws = w2i + c * 8192;
            #pragma unroll
            for (int i = 0; i < 4; ++i) {
                int idx = tid + i * 256;
                CP16(sbWB + idx * 16, ws + idx * 8);
            }
        }
        CP_WAIT();
        __syncthreads();
        #pragma unroll
        for (int k16 = 0; k16 < 4; ++k16) {
            uint2 a[2][2];
            #pragma unroll
            for (int mi = 0; mi < 2; ++mi) {
                const char* ap = smem + SM_HA +
                    ((wm * 2 + mi) * 8 + c * 4 + k16) * 512 + aoff;
                a[mi][0] = *(const uint2*)ap;
                a[mi][1] = *(const uint2*)(ap + 256);
            }
            #pragma unroll
            for (int ni = 0; ni < 8; ++ni) {
                const char* bp = smem + SM_WB + ((wn * 8 + ni) * 4 + k16) * 256 + aoff;
                uint2 b = *(const uint2*)bp;
                domma(acc[0][ni], a[0][0], a[0][1], b);
                domma(acc[1][ni], a[1][0], a[1][1], b);
            }
        }
    }
    __syncthreads();   // layer-2 HA reads done before in-place overwrite

    // epilogue 2: bias + relu -> HA (in place)
    {
        const float* bp = p.b2[gi] + ki * 128;
        #pragma unroll
        for (int ni = 0; ni < 8; ++ni) {
            int col0 = wn * 64 + ni * 8 + 2 * t4;
            float2 bb = *(const float2*)(bp + col0);
            int kt = wn * 4 + (ni >> 1);
            int off = awl + ((ni & 1) << 2);
            #pragma unroll
            for (int mi = 0; mi < 2; ++mi) {
                char* base = smem + SM_HA + ((wm * 2 + mi) * 8 + kt) * 512 + g * 32 + off;
                *(uint32_t*)base = pkh2(fmaxf(acc[mi][ni][0] + bb.x, 0.f),
                                        fmaxf(acc[mi][ni][1] + bb.y, 0.f));
                *(uint32_t*)(base + 256) = pkh2(fmaxf(acc[mi][ni][2] + bb.x, 0.f),
                                                fmaxf(acc[mi][ni][3] + bb.y, 0.f));
                acc[mi][ni][0] = acc[mi][ni][1] = acc[mi][ni][2] = acc[mi][ni][3] = 0.f;
            }
        }
    }
    __syncthreads();

    // ============================ Layer 3 ================================
    {   // W3 image: 64n x 128k = 16KB
        const __half* ws = g_w3i + node * 8192;
        #pragma unroll
        for (int i = 0; i < 4; ++i) {
            int idx = tid + i * 256;
            CP16(sbWB + idx * 16, ws + idx * 8);
        }
    }
    CP_WAIT();
    __syncthreads();

    #pragma unroll
    for (int k16 = 0; k16 < 8; ++k16) {
        uint2 a[2][2];
        #pragma unroll
        for (int mi = 0; mi < 2; ++mi) {
            const char* ap = smem + SM_HA + ((wm * 2 + mi) * 8 + k16) * 512 + aoff;
            a[mi][0] = *(const uint2*)ap;
            a[mi][1] = *(const uint2*)(ap + 256);
        }
        #pragma unroll
        for (int ni = 0; ni < 4; ++ni) {
            const char* bp = smem + SM_WB + ((wn * 4 + ni) * 8 + k16) * 256 + aoff;
            uint2 b = *(const uint2*)bp;
            domma(acc[0][ni], a[0][0], a[0][1], b);
            domma(acc[1][ni], a[1][0], a[1][1], b);
        }
    }

    // epilogue 3: bias, f32 STG.64 direct
    {
        const float* bp = p.b3[gi] + ki * 64;
        const int oj = c_out[node] * 64;
        #pragma unroll
        for (int ni = 0; ni < 4; ++ni) {
            int col0 = wn * 32 + ni * 8 + 2 * t4;
            float2 bb = *(const float2*)(bp + col0);
            #pragma unroll
            for (int mi = 0; mi < 2; ++mi) {
                size_t ro = (size_t)(m0 + wm * 32 + mi * 16 + g) * 1344 + oj + col0;
                *(float2*)(p.out + ro) =
                    make_float2(acc[mi][ni][0] + bb.x, acc[mi][ni][1] + bb.y);
                *(float2*)(p.out + ro + (size_t)8 * 1344) =
                    make_float2(acc[mi][ni][2] + bb.x, acc[mi][ni][3] + bb.y);
            }
        }
    }
}

// ------------------------------ launch -------------------------------------

extern "C" void kernel_launch(void* const* d_in, const int* in_sizes, int n_in,
                              void* d_out, int out_size) {
    (void)n_in; (void)out_size;
    Params p;
    p.x = (const float*)d_in[0];
    int idx = 1;
    for (int gi = 0; gi < 5; ++gi) {
        p.w1[gi] = (const float*)d_in[idx++];
        p.b1[gi] = (const float*)d_in[idx++];
        p.w2[gi] = (const float*)d_in[idx++];
        p.b2[gi] = (const float*)d_in[idx++];
        p.w3[gi] = (const float*)d_in[idx++];
        p.b3[gi] = (const float*)d_in[idx++];
    }
    p.out = (float*)d_out;

    const int B = in_sizes[0] / (21 * 64);

    prep_kernel<<<dim3(192, 21, 3), 256>>>(p);

    cudaFuncSetAttribute(mp6_kernel, cudaFuncAttributeMaxDynamicSharedMemorySize,
                         SMEM_TOTAL);
    dim3 grid(21, B / 128);
    mp6_kernel<<<grid, 256, SMEM_TOTAL>>>(p);
}

// round 7
// speedup vs baseline: 1.9524x; 1.0087x over previous
#include <cuda_runtime.h>
#include <cuda_fp16.h>
#include <cstdint>

// ---------------------------------------------------------------------------
// Round 7: fp16 m16n8k16, warp tile 64x64 (4 warps, 2Mx2N), M_tile=128.
// Double-buffered X and W with cp.async prefetch under the MMA phases.
// 128 thr/CTA, 99KB smem, 2 CTAs/SM. Image layouts identical to R6.
// ---------------------------------------------------------------------------

struct Params {
    const float* x;
    const float* w1[5]; const float* b1[5];
    const float* w2[5]; const float* b2[5];
    const float* w3[5]; const float* b3[5];
    float* out;
};

__constant__ int c_gi[21]  = {0,1,1,1,2,2,3,3,3,3,3,3,3,3,3,3,4,4,4,4,4};
__constant__ int c_ki[21]  = {0,0,1,2,0,1,0,1,2,3,4,5,6,7,8,9,0,1,2,3,4};
__constant__ int c_n[21]   = {6,5,5,5,4,4,3,3,3,3,3,3,3,3,3,3,2,2,2,2,2};
__constant__ int c_out[21] = {0,5,9,13,1,17,2,3,6,7,10,11,14,15,18,19,4,8,12,16,20};
__constant__ int c_nb[21][6] = {
    {0,1,5,9,13,17},
    {0,5,6,1,9,0},  {0,9,10,5,13,0}, {0,13,14,9,17,0},
    {0,1,2,5,0,0},  {0,17,18,13,0,0},
    {1,2,3,0,0,0},  {2,3,4,0,0,0},
    {5,6,7,0,0,0},  {6,7,8,0,0,0},
    {9,10,11,0,0,0},{10,11,12,0,0,0},
    {13,14,15,0,0,0},{14,15,16,0,0,0},
    {17,18,19,0,0,0},{18,19,20,0,0,0},
    {3,4,0,0,0,0},  {7,8,0,0,0,0}, {11,12,0,0,0,0},
    {15,16,0,0,0,0},{19,20,0,0,0,0}
};
// per-node half-offset of W1 image (chunks of 8192 halves = one 64-k slab)
__constant__ int c_w1i_off[21] = {
    0,49152,90112,131072,172032,204800,
    237568,262144,286720,311296,335872,360448,385024,409600,434176,458752,
    483328,499712,516096,532480,548864
};

// Pre-shuffled fp16 weight images (exact SMEM byte layout)
__device__ __align__(16) __half g_w1i[565248];
__device__ __align__(16) __half g_w2i[344064];   // 21 * 2 * 8192
__device__ __align__(16) __half g_w3i[172032];   // 21 * 8192

// SMEM map (bytes). Tiles: 16 rows x 32B. HA 512B, XA 528B (pad), WB 256B.
#define SM_HA 0                      // 64 tiles * 512 = 32768
#define SM_XA 32768                  // 2 bufs * 32 tiles * 528 = 33792
#define XA_BUF 16896
#define SM_WB 66560                  // 2 bufs * 16384
#define WB_BUF 16384
#define SMEM_TOTAL 99328

__device__ __forceinline__ uint32_t pkh2(float lo, float hi) {
    uint32_t r;   // low half = lo
    asm("cvt.rn.f16x2.f32 %0, %1, %2;" : "=r"(r) : "f"(hi), "f"(lo));
    return r;
}

__device__ __forceinline__ void mma16(float c[4],
                                      uint32_t a0, uint32_t a1, uint32_t a2, uint32_t a3,
                                      uint32_t b0, uint32_t b1) {
    asm volatile(
        "mma.sync.aligned.m16n8k16.row.col.f32.f16.f16.f32 "
        "{%0,%1,%2,%3},{%4,%5,%6,%7},{%8,%9},{%0,%1,%2,%3};"
        : "+f"(c[0]), "+f"(c[1]), "+f"(c[2]), "+f"(c[3])
        : "r"(a0), "r"(a1), "r"(a2), "r"(a3), "r"(b0), "r"(b1));
}
__device__ __forceinline__ void domma(float c[4], uint2 Pg, uint2 Pg8, uint2 Pb) {
    mma16(c, Pg.x, Pg8.x, Pg.y, Pg8.y, Pb.x, Pb.y);
}

#define CP16(dst, src) \
    asm volatile("cp.async.ca.shared.global [%0], [%1], 16;" :: "r"(dst), "l"(src))
#define CP_COMMIT() asm volatile("cp.async.commit_group;" ::: "memory")
#define CP_WAIT0()  asm volatile("cp.async.wait_group 0;" ::: "memory")

__device__ __forceinline__ uint32_t smem_u32(const void* p) {
    uint32_t a;
    asm("{ .reg .u64 t; cvta.to.shared.u64 t, %1; cvt.u32.u64 %0, t; }"
        : "=r"(a) : "l"(p));
    return a;
}

// ------------------------------ prep kernel --------------------------------
// Identical to R6 (verified): B tile stride = 128 halves.
__device__ __forceinline__ int imgh(int n, int k, int K16, int NK16c) {
    int jw = (k & 15) >> 1, lo = k & 1;
    int rn = n & 7, NB = n >> 3, s = (rn >> 2) & 1;
    return (NB * NK16c + K16) * 128 + rn * 16 +
           ((((jw >> 1) & 1) ^ s) << 3) + ((jw & 1) << 2) + ((jw >> 2) << 1) + lo;
}

__global__ void prep_kernel(Params p) {
    const int node = blockIdx.y;
    const int gi = c_gi[node], ki = c_ki[node], nnb = c_n[node];
    const int i = blockIdx.x * 256 + threadIdx.x;
    if (blockIdx.z == 0) {
        const int K1 = nnb * 64;
        if (i >= 128 * K1) return;
        const int k = i >> 7, n = i & 127;
        float v = p.w1[gi][((size_t)ki * K1 + k) * 128 + n];
        g_w1i[c_w1i_off[node] + (k >> 6) * 8192 + imgh(n, k, (k >> 4) & 3, 4)] =
            __float2half_rn(v);
    } else if (blockIdx.z == 1) {
        if (i >= 16384) return;
        const int k = i >> 7, n = i & 127;
        float v = p.w2[gi][(size_t)ki * 16384 + (size_t)k * 128 + n];
        g_w2i[node * 16384 + (k >> 6) * 8192 + imgh(n, k, (k >> 4) & 3, 4)] =
            __float2half_rn(v);
    } else {
        if (i >= 8192) return;
        const int k = i >> 6, n = i & 63;
        float v = p.w3[gi][(size_t)ki * 8192 + (size_t)k * 64 + n];
        g_w3i[node * 8192 + imgh(n, k, k >> 4, 8)] = __float2half_rn(v);
    }
}

// ------------------------------ main kernel --------------------------------

__global__ __launch_bounds__(128, 2)
void mp7_kernel(Params p) {
    extern __shared__ char smem[];
    const int tid = threadIdx.x;
    const int w = tid >> 5, lane = tid & 31;
    const int g = lane >> 2, t4 = lane & 3;
    const int node = blockIdx.x;
    const int m0 = blockIdx.y * 128;
    const int gi = c_gi[node], ki = c_ki[node], nnb = c_n[node];
    const int wm = w & 1, wn = w >> 1;          // 2M x 2N grid of 64x64 tiles
    const int sg = (g >> 2) & 1;
    const int awl  = (((t4 >> 1) ^ sg) << 4) + ((t4 & 1) << 3);
    const int aoff = g * 32 + awl;

    const uint32_t sbWB = smem_u32(smem + SM_WB);

    float acc[4][8][4];
    #pragma unroll
    for (int mi = 0; mi < 4; ++mi)
        #pragma unroll
        for (int ni = 0; ni < 8; ++ni)
            #pragma unroll
            for (int r = 0; r < 4; ++r) acc[mi][ni][r] = 0.f;

    // ---- helpers (inlined) ----
    #define ISSUE_W(ws, buf) do {                                         \
        uint32_t _d = sbWB + (buf) * WB_BUF;                              \
        const __half* _s = (ws);                                          \
        _Pragma("unroll")                                                 \
        for (int _i = 0; _i < 8; ++_i) {                                  \
            int _idx = tid + _i * 128;                                    \
            CP16(_d + _idx * 16, _s + _idx * 8);                          \
        }                                                                 \
        CP_COMMIT();                                                      \
    } while (0)

    #define STORE_X(joint, buf) do {                                      \
        const float* _xb = p.x + (size_t)m0 * 1344 + (joint) * 64;        \
        char* _xa = smem + SM_XA + (buf) * XA_BUF;                        \
        _Pragma("unroll")                                                 \
        for (int _i = 0; _i < 4; ++_i) {                                  \
            int _v = tid + _i * 128;                                      \
            int _m = _v >> 2, _kt = _v & 3;                               \
            const float* _s = _xb + (size_t)_m * 1344 + _kt * 16;         \
            float4 A0 = *(const float4*)_s;                               \
            float4 A1 = *(const float4*)(_s + 4);                         \
            float4 A2 = *(const float4*)(_s + 8);                         \
            float4 A3 = *(const float4*)(_s + 12);                        \
            uint4 q0 = make_uint4(pkh2(A0.x, A0.y), pkh2(A2.x, A2.y),     \
                                  pkh2(A0.z, A0.w), pkh2(A2.z, A2.w));    \
            uint4 q1 = make_uint4(pkh2(A1.x, A1.y), pkh2(A3.x, A3.y),     \
                                  pkh2(A1.z, A1.w), pkh2(A3.z, A3.w));    \
            int _r = _m & 15, _R = _m >> 4;                               \
            char* _dst = _xa + (_R * 4 + _kt) * 528 + _r * 32;            \
            int _sw = (_r & 4) << 2;                                      \
            *(uint4*)(_dst + _sw) = q0;                                   \
            *(uint4*)(_dst + (16 ^ _sw)) = q1;                            \
        }                                                                 \
    } while (0)

    // ============================ Layer 1 ================================
    const __half* w1i = g_w1i + c_w1i_off[node];
    const __half* w2i = g_w2i + node * 16384;
    const __half* w3i = g_w3i + node * 8192;

    // prologue: chunk 0 into buffers 0
    ISSUE_W(w1i, 0);
    STORE_X(c_nb[node][0], 0);
    CP_WAIT0();
    __syncthreads();

    #pragma unroll 1
    for (int c = 0; c < nnb; ++c) {
        const int cu = c & 1, nx = cu ^ 1;
        // prefetch next chunk (or W2 chunk0) under this chunk's MMA
        if (c + 1 < nnb) {
            ISSUE_W(w1i + (c + 1) * 8192, nx);
            STORE_X(c_nb[node][c + 1], nx);
        } else {
            ISSUE_W(w2i, nx);
        }
        const char* xa = smem + SM_XA + cu * XA_BUF;
        const char* wb = smem + SM_WB + cu * WB_BUF;
        #pragma unroll
        for (int k16 = 0; k16 < 4; ++k16) {
            uint2 a[4][2];
            #pragma unroll
            for (int mi = 0; mi < 4; ++mi) {
                const char* ap = xa + ((wm * 4 + mi) * 4 + k16) * 528 + aoff;
                a[mi][0] = *(const uint2*)ap;
                a[mi][1] = *(const uint2*)(ap + 256);
            }
            #pragma unroll
            for (int ni = 0; ni < 8; ++ni) {
                const char* bp = wb + ((wn * 8 + ni) * 4 + k16) * 256 + aoff;
                uint2 b = *(const uint2*)bp;
                #pragma unroll
                for (int mi = 0; mi < 4; ++mi)
                    domma(acc[mi][ni], a[mi][0], a[mi][1], b);
            }
        }
        CP_WAIT0();
        __syncthreads();
    }
    const int b0 = nnb & 1;   // W2 chunk0 buffer

    // epilogue 1: prefetch W2 chunk1, bias + relu -> HA
    ISSUE_W(w2i + 8192, b0 ^ 1);
    {
        const float* bp = p.b1[gi] + ki * 128;
        #pragma unroll
        for (int ni = 0; ni < 8; ++ni) {
            int col0 = wn * 64 + ni * 8 + 2 * t4;
            float2 bb = *(const float2*)(bp + col0);
            int kt = wn * 4 + (ni >> 1);
            int off = awl + ((ni & 1) << 2);
            #pragma unroll
            for (int mi = 0; mi < 4; ++mi) {
                char* base = smem + SM_HA + ((wm * 4 + mi) * 8 + kt) * 512 + g * 32 + off;
                *(uint32_t*)base = pkh2(fmaxf(acc[mi][ni][0] + bb.x, 0.f),
                                        fmaxf(acc[mi][ni][1] + bb.y, 0.f));
                *(uint32_t*)(base + 256) = pkh2(fmaxf(acc[mi][ni][2] + bb.x, 0.f),
                                                fmaxf(acc[mi][ni][3] + bb.y, 0.f));
                acc[mi][ni][0] = acc[mi][ni][1] = acc[mi][ni][2] = acc[mi][ni][3] = 0.f;
            }
        }
    }
    __syncthreads();

    // ============================ Layer 2 ================================
    #pragma unroll 1
    for (int c = 0; c < 2; ++c) {
        if (c == 1) ISSUE_W(w3i, b0);   // prefetch W3 into chunk0's buffer
        const char* wb = smem + SM_WB + ((c == 0) ? b0 : (b0 ^ 1)) * WB_BUF;
        #pragma unroll
        for (int k16 = 0; k16 < 4; ++k16) {
            uint2 a[4][2];
            #pragma unroll
            for (int mi = 0; mi < 4; ++mi) {
                const char* ap = smem + SM_HA +
                    ((wm * 4 + mi) * 8 + c * 4 + k16) * 512 + aoff;
                a[mi][0] = *(const uint2*)ap;
                a[mi][1] = *(const uint2*)(ap + 256);
            }
            #pragma unroll
            for (int ni = 0; ni < 8; ++ni) {
                const char* bp = wb + ((wn * 8 + ni) * 4 + k16) * 256 + aoff;
                uint2 b = *(const uint2*)bp;
                #pragma unroll
                for (int mi = 0; mi < 4; ++mi)
                    domma(acc[mi][ni], a[mi][0], a[mi][1], b);
            }
        }
        CP_WAIT0();
        __syncthreads();
    }

    // epilogue 2: bias + relu -> HA (in place; layer-2 reads done at barrier)
    {
        const float* bp = p.b2[gi] + ki * 128;
        #pragma unroll
        for (int ni = 0; ni < 8; ++ni) {
            int col0 = wn * 64 + ni * 8 + 2 * t4;
            float2 bb = *(const float2*)(bp + col0);
            int kt = wn * 4 + (ni >> 1);
            int off = awl + ((ni & 1) << 2);
            #pragma unroll
            for (int mi = 0; mi < 4; ++mi) {
                char* base = smem + SM_HA + ((wm * 4 + mi) * 8 + kt) * 512 + g * 32 + off;
                *(uint32_t*)base = pkh2(fmaxf(acc[mi][ni][0] + bb.x, 0.f),
                                        fmaxf(acc[mi][ni][1] + bb.y, 0.f));
                *(uint32_t*)(base + 256) = pkh2(fmaxf(acc[mi][ni][2] + bb.x, 0.f),
                                                fmaxf(acc[mi][ni][3] + bb.y, 0.f));
                acc[mi][ni][0] = acc[mi][ni][1] = acc[mi][ni][2] = acc[mi][ni][3] = 0.f;
            }
        }
    }
    __syncthreads();

    // ============================ Layer 3 ================================
    {
        const char* wb = smem + SM_WB + b0 * WB_BUF;   // W3 (waited at L2 end)
        #pragma unroll
        for (int k16 = 0; k16 < 8; ++k16) {
            uint2 a[4][2];
            #pragma unroll
            for (int mi = 0; mi < 4; ++mi) {
                const char* ap = smem + SM_HA + ((wm * 4 + mi) * 8 + k16) * 512 + aoff;
                a[mi][0] = *(const uint2*)ap;
                a[mi][1] = *(const uint2*)(ap + 256);
            }
            #pragma unroll
            for (int ni = 0; ni < 4; ++ni) {
                const char* bp = wb + ((wn * 4 + ni) * 8 + k16) * 256 + aoff;
                uint2 b = *(const uint2*)bp;
                #pragma unroll
                for (int mi = 0; mi < 4; ++mi)
                    domma(acc[mi][ni], a[mi][0], a[mi][1], b);
            }
        }
    }

    // epilogue 3: bias, f32 STG.64 direct
    {
        const float* bp = p.b3[gi] + ki * 64;
        const int oj = c_out[node] * 64;
        #pragma unroll
        for (int ni = 0; ni < 4; ++ni) {
            int col0 = wn * 32 + ni * 8 + 2 * t4;
            float2 bb = *(const float2*)(bp + col0);
            #pragma unroll
            for (int mi = 0; mi < 4; ++mi) {
                size_t ro = (size_t)(m0 + wm * 64 + mi * 16 + g) * 1344 + oj + col0;
                *(float2*)(p.out + ro) =
                    make_float2(acc[mi][ni][0] + bb.x, acc[mi][ni][1] + bb.y);
                *(float2*)(p.out + ro + (size_t)8 * 1344) =
                    make_float2(acc[mi][ni][2] + bb.x, acc[mi][ni][3] + bb.y);
            }
        }
    }
    #undef ISSUE_W
    #undef STORE_X
}

// ------------------------------ launch -------------------------------------

extern "C" void kernel_launch(void* const* d_in, const int* in_sizes, int n_in,
                              void* d_out, int out_size) {
    (void)n_in; (void)out_size;
    Params p;
    p.x = (const float*)d_in[0];
    int idx = 1;
    for (int gi = 0; gi < 5; ++gi) {
        p.w1[gi] = (const float*)d_in[idx++];
        p.b1[gi] = (const float*)d_in[idx++];
        p.w2[gi] = (const float*)d_in[idx++];
        p.b2[gi] = (const float*)d_in[idx++];
        p.w3[gi] = (const float*)d_in[idx++];
        p.b3[gi] = (const float*)d_in[idx++];
    }
    p.out = (float*)d_out;

    const int B = in_sizes[0] / (21 * 64);

    prep_kernel<<<dim3(192, 21, 3), 256>>>(p);

    cudaFuncSetAttribute(mp7_kernel, cudaFuncAttributeMaxDynamicSharedMemorySize,
                         SMEM_TOTAL);
    dim3 grid(21, B / 128);
    mp7_kernel<<<grid, 128, SMEM_TOTAL>>>(p);
}